// round 8
// baseline (speedup 1.0000x reference)
#include <cuda_runtime.h>

// Problem constants
#define Bb 512
#define Ss 1024
#define Ff 64
#define Ll 128
#define Gg 512   // 4*L
#define BT 4     // batch rows per CTA
#define CR 20    // W cols per gate held in registers
#define CS 108   // W cols per gate streamed from smem (CR + CS = 128)
#define NKG 27   // CS / 4
#define HP 132   // padded h row stride in floats (breaks bank conflicts, keeps 16B align)

typedef unsigned long long ull;

// ------------------------- device scratch -------------------------
__device__ float g_gx[(size_t)Bb * Ss * Gg];    // x-proj + enc bias, permuted slot layout (1 GB)
__device__ float g_hall[(size_t)Bb * Ss * Ll];  // decoder h states (256 MB)
__device__ float g_weff[Gg * Ll];               // W_hh_dec + W_ih_dec @ W_dense
__device__ float g_benc[Gg];
__device__ float g_beff[Gg];
__device__ float g_hn[Bb * Ll];
__device__ float g_cn[Bb * Ll];

// ------------------------- helpers -------------------------
__device__ __forceinline__ ull pk(float x, float y) {
    ull r; asm("mov.b64 %0, {%1, %2};" : "=l"(r) : "f"(x), "f"(y)); return r;
}
__device__ __forceinline__ void upk(ull v, float& x, float& y) {
    asm("mov.b64 {%0, %1}, %2;" : "=f"(x), "=f"(y) : "l"(v));
}
__device__ __forceinline__ void fma2(ull& d, ull a, ull b) {
    asm("fma.rn.f32x2 %0, %1, %2, %0;" : "+l"(d) : "l"(a), "l"(b));
}
__device__ __forceinline__ float ex2a(float x) {
    float r; asm("ex2.approx.f32 %0, %1;" : "=f"(r) : "f"(x)); return r;
}
__device__ __forceinline__ float rcpa(float x) {
    float r; asm("rcp.approx.f32 %0, %1;" : "=f"(r) : "f"(x)); return r;
}
__device__ __forceinline__ float fsig(float x) {
    return rcpa(1.0f + ex2a(-1.4426950408889634f * x));
}
__device__ __forceinline__ float ftanh(float x) {
    return fmaf(2.0f, rcpa(1.0f + ex2a(-2.8853900817779268f * x)), -1.0f);
}

// ------------------------- setup: fold decoder matrices -------------------------
__global__ void setup_kernel(const float* __restrict__ Wih_d,
                             const float* __restrict__ Whh_d,
                             const float* __restrict__ bih_d,
                             const float* __restrict__ bhh_d,
                             const float* __restrict__ Wdn,
                             const float* __restrict__ bdn,
                             const float* __restrict__ bih_e,
                             const float* __restrict__ bhh_e) {
    int j = blockIdx.x;   // gate 0..511
    int k = threadIdx.x;  // latent 0..127
    float s = 0.0f;
    for (int m = 0; m < Ff; m++) s += Wih_d[j * Ff + m] * Wdn[m * Ll + k];
    g_weff[j * Ll + k] = Whh_d[j * Ll + k] + s;
    if (k == 0) {
        float bs = bih_d[j] + bhh_d[j];
        for (int m = 0; m < Ff; m++) bs += Wih_d[j * Ff + m] * bdn[m];
        g_beff[j] = bs;
        g_benc[j] = bih_e[j] + bhh_e[j];
    }
}

// ------------------------- x-projection GEMM -------------------------
// Writes gx in PERMUTED slot layout: slot s = l*4 + gi  <->  gate gi*128 + l.
// Thread handles slots sA=t_, sB=t_+256 using W_ih row perm(s); writes stay coalesced.
__global__ void __launch_bounds__(256, 1)
xproj_kernel(const float* __restrict__ x, const float* __restrict__ Wih) {
    extern __shared__ char smraw[];
    ulonglong2* Wsm = (ulonglong2*)smraw;            // [16][512] float4 = 128KB
    float* xs = (float*)(smraw + 16 * 512 * 16);     // [32][64] = 8KB
    const int t_ = threadIdx.x;
    const int sA = t_, sB = t_ + 256;
    const int gA = (sA & 3) * 128 + (sA >> 2);
    const int gB = (sB & 3) * 128 + (sB >> 2);

    const float4* wa = (const float4*)(Wih + gA * Ff);
    const float4* wb = (const float4*)(Wih + gB * Ff);
#pragma unroll
    for (int kg = 0; kg < 16; kg++) {
        ((float4*)Wsm)[kg * 512 + sA] = wa[kg];
        ((float4*)Wsm)[kg * 512 + sB] = wb[kg];
    }
    const float bA = g_benc[gA], bB = g_benc[gB];
    const size_t row0 = (size_t)blockIdx.x * 32;

    ((float4*)xs)[t_]       = ((const float4*)x)[row0 * 16 + t_];
    ((float4*)xs)[t_ + 256] = ((const float4*)x)[row0 * 16 + t_ + 256];
    __syncthreads();

    ull aA[32], aB[32];
#pragma unroll
    for (int r = 0; r < 32; r++) { aA[r] = 0ull; aB[r] = 0ull; }

#pragma unroll 4
    for (int kg = 0; kg < 16; kg++) {
        ulonglong2 wAv = Wsm[kg * 512 + sA];
        ulonglong2 wBv = Wsm[kg * 512 + sB];
#pragma unroll
        for (int r = 0; r < 32; r++) {
            ulonglong2 hh = *(const ulonglong2*)(xs + r * Ff + 4 * kg);
            fma2(aA[r], hh.x, wAv.x); fma2(aA[r], hh.y, wAv.y);
            fma2(aB[r], hh.x, wBv.x); fma2(aB[r], hh.y, wBv.y);
        }
    }
#pragma unroll
    for (int r = 0; r < 32; r++) {
        float lo, hi;
        upk(aA[r], lo, hi); g_gx[(row0 + r) * Gg + sA] = lo + hi + bA;
        upk(aB[r], lo, hi); g_gx[(row0 + r) * Gg + sB] = lo + hi + bB;
    }
}

// ------------------------- persistent encoder recurrence -------------------------
// 512 threads, tid = l*4 + r: thread owns ALL FOUR gates of (latent l, batch row r).
// c is thread-local; ONE barrier per step via double-buffered h.
// W per gate: cols [0,CR) in registers, cols [CR,128) from smem laid out [kg][gi][l]
// (l-contiguous 16B chunks -> conflict-free 1-wavefront LDS.128).
__global__ void __launch_bounds__(512, 1)
enc_kernel(const float* __restrict__ Whh) {
    extern __shared__ char smraw[];
    float4* Wsm = (float4*)smraw;                        // NKG*4*128 float4 = 221184B
    float* hs = (float*)(smraw + NKG * 4 * 128 * 16);    // [2][4][HP]
    const int tid = threadIdx.x;
    const int l = tid >> 2, r = tid & 3;
    const int b0 = blockIdx.x * BT;

    ull Wr[4][CR / 2];
#pragma unroll
    for (int gi = 0; gi < 4; gi++) {
        const float* wrow = Whh + (gi * Ll + l) * Ll;
#pragma unroll
        for (int q = 0; q < CR / 4; q++) {
            float4 v = *(const float4*)(wrow + 4 * q);
            Wr[gi][2 * q] = pk(v.x, v.y); Wr[gi][2 * q + 1] = pk(v.z, v.w);
        }
#pragma unroll
        for (int kg = 0; kg < NKG; kg++)
            Wsm[(kg * 4 + gi) * Ll + l] = *(const float4*)(wrow + CR + 4 * kg);
    }
    hs[r * HP + l] = 0.0f;
    float c = 0.0f, hnew = 0.0f;
    __syncthreads();

    for (int t = 0; t < Ss; t++) {
        float4 gx = *(const float4*)(g_gx + ((size_t)(b0 + r) * Ss + t) * Gg + l * 4);
        const float* h = hs + (t & 1) * (4 * HP) + r * HP;
        ull a0 = 0, a1 = 0, a2 = 0, a3 = 0;
#pragma unroll
        for (int q = 0; q < CR / 4; q++) {
            ulonglong2 h2 = *(const ulonglong2*)(h + 4 * q);
            fma2(a0, h2.x, Wr[0][2 * q]); fma2(a0, h2.y, Wr[0][2 * q + 1]);
            fma2(a1, h2.x, Wr[1][2 * q]); fma2(a1, h2.y, Wr[1][2 * q + 1]);
            fma2(a2, h2.x, Wr[2][2 * q]); fma2(a2, h2.y, Wr[2][2 * q + 1]);
            fma2(a3, h2.x, Wr[3][2 * q]); fma2(a3, h2.y, Wr[3][2 * q + 1]);
        }
#pragma unroll
        for (int kg = 0; kg < NKG; kg++) {
            ulonglong2 h2 = *(const ulonglong2*)(h + CR + 4 * kg);
            ulonglong2 w0 = *(const ulonglong2*)&Wsm[(kg * 4 + 0) * Ll + l];
            ulonglong2 w1 = *(const ulonglong2*)&Wsm[(kg * 4 + 1) * Ll + l];
            ulonglong2 w2 = *(const ulonglong2*)&Wsm[(kg * 4 + 2) * Ll + l];
            ulonglong2 w3 = *(const ulonglong2*)&Wsm[(kg * 4 + 3) * Ll + l];
            fma2(a0, h2.x, w0.x); fma2(a0, h2.y, w0.y);
            fma2(a1, h2.x, w1.x); fma2(a1, h2.y, w1.y);
            fma2(a2, h2.x, w2.x); fma2(a2, h2.y, w2.y);
            fma2(a3, h2.x, w3.x); fma2(a3, h2.y, w3.y);
        }
        float lo, hi;
        upk(a0, lo, hi); float vi = lo + hi + gx.x;
        upk(a1, lo, hi); float vf = lo + hi + gx.y;
        upk(a2, lo, hi); float vg = lo + hi + gx.z;
        upk(a3, lo, hi); float vo = lo + hi + gx.w;
        c = fsig(vf) * c + fsig(vi) * ftanh(vg);
        hnew = fsig(vo) * ftanh(c);
        hs[((t + 1) & 1) * (4 * HP) + r * HP + l] = hnew;
        __syncthreads();
    }
    g_hn[(b0 + r) * Ll + l] = hnew;
    g_cn[(b0 + r) * Ll + l] = c;
}

// ------------------------- persistent decoder recurrence -------------------------
// Same structure on W_eff. Per step: one sector-perfect STG of h to g_hall;
// the dense read-out + flip is a separate embarrassingly-parallel kernel.
__global__ void __launch_bounds__(512, 1)
dec_kernel() {
    extern __shared__ char smraw[];
    float4* Wsm = (float4*)smraw;
    float* hs = (float*)(smraw + NKG * 4 * 128 * 16);
    const int tid = threadIdx.x;
    const int l = tid >> 2, r = tid & 3;
    const int b0 = blockIdx.x * BT;

    ull Wr[4][CR / 2];
    float be[4];
#pragma unroll
    for (int gi = 0; gi < 4; gi++) {
        const float* wrow = g_weff + (gi * Ll + l) * Ll;
#pragma unroll
        for (int q = 0; q < CR / 4; q++) {
            float4 v = *(const float4*)(wrow + 4 * q);
            Wr[gi][2 * q] = pk(v.x, v.y); Wr[gi][2 * q + 1] = pk(v.z, v.w);
        }
#pragma unroll
        for (int kg = 0; kg < NKG; kg++)
            Wsm[(kg * 4 + gi) * Ll + l] = *(const float4*)(wrow + CR + 4 * kg);
        be[gi] = g_beff[gi * Ll + l];
    }
    float c = g_cn[(b0 + r) * Ll + l];
    hs[r * HP + l] = g_hn[(b0 + r) * Ll + l];
    __syncthreads();

    float* hout = g_hall + ((size_t)(b0 + r) * Ss) * Ll + l;
    for (int t = 0; t < Ss; t++) {
        const float* h = hs + (t & 1) * (4 * HP) + r * HP;
        ull a0 = 0, a1 = 0, a2 = 0, a3 = 0;
#pragma unroll
        for (int q = 0; q < CR / 4; q++) {
            ulonglong2 h2 = *(const ulonglong2*)(h + 4 * q);
            fma2(a0, h2.x, Wr[0][2 * q]); fma2(a0, h2.y, Wr[0][2 * q + 1]);
            fma2(a1, h2.x, Wr[1][2 * q]); fma2(a1, h2.y, Wr[1][2 * q + 1]);
            fma2(a2, h2.x, Wr[2][2 * q]); fma2(a2, h2.y, Wr[2][2 * q + 1]);
            fma2(a3, h2.x, Wr[3][2 * q]); fma2(a3, h2.y, Wr[3][2 * q + 1]);
        }
#pragma unroll
        for (int kg = 0; kg < NKG; kg++) {
            ulonglong2 h2 = *(const ulonglong2*)(h + CR + 4 * kg);
            ulonglong2 w0 = *(const ulonglong2*)&Wsm[(kg * 4 + 0) * Ll + l];
            ulonglong2 w1 = *(const ulonglong2*)&Wsm[(kg * 4 + 1) * Ll + l];
            ulonglong2 w2 = *(const ulonglong2*)&Wsm[(kg * 4 + 2) * Ll + l];
            ulonglong2 w3 = *(const ulonglong2*)&Wsm[(kg * 4 + 3) * Ll + l];
            fma2(a0, h2.x, w0.x); fma2(a0, h2.y, w0.y);
            fma2(a1, h2.x, w1.x); fma2(a1, h2.y, w1.y);
            fma2(a2, h2.x, w2.x); fma2(a2, h2.y, w2.y);
            fma2(a3, h2.x, w3.x); fma2(a3, h2.y, w3.y);
        }
        float lo, hi;
        upk(a0, lo, hi); float vi = lo + hi + be[0];
        upk(a1, lo, hi); float vf = lo + hi + be[1];
        upk(a2, lo, hi); float vg = lo + hi + be[2];
        upk(a3, lo, hi); float vo = lo + hi + be[3];
        c = fsig(vf) * c + fsig(vi) * ftanh(vg);
        float hnew = fsig(vo) * ftanh(c);
        hs[((t + 1) & 1) * (4 * HP) + r * HP + l] = hnew;
        hout[(size_t)t * Ll] = hnew;   // g_hall[b0+r][t][l] = H_{t+1}
        __syncthreads();
    }
}

// ------------------------- output GEMM + flip -------------------------
// out[b][S-1-t][f] = bdn[f] + g_hall[b][t][:] @ W_dense[f][:]
// CTA: 128 g_hall rows staged to smem; thread (f = tid&63, rg = tid>>6) does 32 rows,
// W_dense row in registers, h via broadcast LDS.
__global__ void __launch_bounds__(256, 1)
out_kernel(const float* __restrict__ Wdn, const float* __restrict__ bdn,
           float* __restrict__ out) {
    extern __shared__ float hsm[];   // [128][128] = 64KB
    const int tid = threadIdx.x;
    const size_t row0 = (size_t)blockIdx.x * 128;
    for (int i = tid; i < 128 * Ll / 4; i += 256)
        ((float4*)hsm)[i] = ((const float4*)g_hall)[row0 * (Ll / 4) + i];

    const int f = tid & 63, rg = tid >> 6;
    ull Wd[64];
    const float4* wd = (const float4*)(Wdn + f * Ll);
#pragma unroll
    for (int q = 0; q < 32; q++) {
        float4 v = wd[q];
        Wd[2 * q] = pk(v.x, v.y); Wd[2 * q + 1] = pk(v.z, v.w);
    }
    const float bv = bdn[f];
    __syncthreads();

#pragma unroll 1
    for (int rr = 0; rr < 32; rr += 2) {
        int row = rg * 32 + rr;
        ull a0 = 0, a1 = 0;
#pragma unroll
        for (int q = 0; q < 32; q++) {
            ulonglong2 h0 = *(const ulonglong2*)(hsm + row * Ll + 4 * q);
            ulonglong2 h1 = *(const ulonglong2*)(hsm + (row + 1) * Ll + 4 * q);
            fma2(a0, h0.x, Wd[2 * q]); fma2(a0, h0.y, Wd[2 * q + 1]);
            fma2(a1, h1.x, Wd[2 * q]); fma2(a1, h1.y, Wd[2 * q + 1]);
        }
        float lo, hi;
        upk(a0, lo, hi); float s0 = lo + hi + bv;
        upk(a1, lo, hi); float s1 = lo + hi + bv;
        size_t g0 = row0 + row;
        size_t b_ = g0 >> 10; int t_ = (int)(g0 & 1023);
        out[(b_ * Ss + (size_t)(Ss - 1 - t_)) * Ff + f] = s0;
        g0 += 1;
        b_ = g0 >> 10; t_ = (int)(g0 & 1023);
        out[(b_ * Ss + (size_t)(Ss - 1 - t_)) * Ff + f] = s1;
    }
}

// ------------------------- launch -------------------------
extern "C" void kernel_launch(void* const* d_in, const int* in_sizes, int n_in,
                              void* d_out, int out_size) {
    const float* x     = (const float*)d_in[0];
    const float* Wih_e = (const float*)d_in[1];
    const float* Whh_e = (const float*)d_in[2];
    const float* bih_e = (const float*)d_in[3];
    const float* bhh_e = (const float*)d_in[4];
    const float* Wih_d = (const float*)d_in[5];
    const float* Whh_d = (const float*)d_in[6];
    const float* bih_d = (const float*)d_in[7];
    const float* bhh_d = (const float*)d_in[8];
    const float* Wdn   = (const float*)d_in[9];
    const float* bdn   = (const float*)d_in[10];
    float* out = (float*)d_out;

    const int SM_X = 16 * 512 * 16 + 32 * 64 * 4;          // 139264
    const int SM_R = NKG * 4 * 128 * 16 + 2 * 4 * HP * 4;  // 221184 + 4224 = 225408
    const int SM_O = 128 * Ll * 4;                         // 65536

    cudaFuncSetAttribute(xproj_kernel, cudaFuncAttributeMaxDynamicSharedMemorySize, SM_X);
    cudaFuncSetAttribute(enc_kernel,   cudaFuncAttributeMaxDynamicSharedMemorySize, SM_R);
    cudaFuncSetAttribute(dec_kernel,   cudaFuncAttributeMaxDynamicSharedMemorySize, SM_R);
    cudaFuncSetAttribute(out_kernel,   cudaFuncAttributeMaxDynamicSharedMemorySize, SM_O);

    setup_kernel<<<Gg, Ll>>>(Wih_d, Whh_d, bih_d, bhh_d, Wdn, bdn, bih_e, bhh_e);
    xproj_kernel<<<(Bb * Ss) / 32, 256, SM_X>>>(x, Wih_e);
    enc_kernel<<<Bb / BT, 512, SM_R>>>(Whh_e);
    dec_kernel<<<Bb / BT, 512, SM_R>>>();
    out_kernel<<<(Bb * Ss) / 128, 256, SM_O>>>(Wdn, bdn, out);
}